// round 2
// baseline (speedup 1.0000x reference)
#include <cuda_runtime.h>
#include <math.h>

// Problem constants
#define B_    16384
#define F_    64
#define H_    512
#define C_    512
#define NBINS 30
#define MULT_ 91            // 3*NBINS+1
#define NOUT  (F_*MULT_)    // 5824
#define NBLK  3

// ----------------------------------------------------------------------------
// Device scratch (no allocations allowed)
// ----------------------------------------------------------------------------
__device__ float g_WinM [F_*H_];
__device__ float g_WhhM [2*NBLK*H_*H_];     // [0..2]=Wb1 masked, [3..5]=Wb2 masked
__device__ float g_WoutM[H_*NOUT];
__device__ float g_t[B_*H_];
__device__ float g_u[B_*H_];
__device__ float g_v[B_*H_];
__device__ float g_g[B_*H_];
__device__ float g_P[(size_t)B_*NOUT];

// ----------------------------------------------------------------------------
// Mask prep kernels (MADE degree masks, applied to weights once per launch)
// d_h[j] = j % (F-1) + 1
// ----------------------------------------------------------------------------
__global__ void mask_in_kernel(const float* __restrict__ W, float* __restrict__ out) {
    int x = blockIdx.x * blockDim.x + threadIdx.x;
    if (x >= F_*H_) return;
    int f = x / H_, j = x % H_;
    int dh = j % (F_-1) + 1;
    out[x] = (dh >= f + 1) ? W[x] : 0.f;
}

__global__ void mask_hh_kernel(const float* __restrict__ W, float* __restrict__ out, int total) {
    int x = blockIdx.x * blockDim.x + threadIdx.x;
    if (x >= total) return;
    int ij = x % (H_*H_);
    int i = ij / H_, j = ij % H_;
    int di = i % (F_-1) + 1, dj = j % (F_-1) + 1;
    out[x] = (dj >= di) ? W[x] : 0.f;
}

__global__ void mask_out_kernel(const float* __restrict__ W, float* __restrict__ out) {
    int x = blockIdx.x * blockDim.x + threadIdx.x;
    if (x >= H_*NOUT) return;
    int j = x / NOUT, k = x % NOUT;
    int dj   = j % (F_-1) + 1;
    int dout = k / MULT_ + 1;
    out[x] = (dout > dj) ? W[x] : 0.f;
}

// ----------------------------------------------------------------------------
// Tiled fp32 SGEMM: C[M,N] = op(A[M,K]) @ W[K,N] (+ bias) (+ C)
// BM=BN=64, BK=16, 256 threads, 4x4 micro-tile per thread.
// All problem dims are multiples of tile sizes -> no bounds checks.
// ----------------------------------------------------------------------------
#define BM 64
#define BN 64
#define BK 16

template<bool RELU_A, bool ACCUM, bool BIAS>
__global__ void sgemm_kernel(const float* __restrict__ A, const float* __restrict__ W,
                             const float* __restrict__ bias, float* __restrict__ C,
                             int M, int N, int K) {
    __shared__ float As[BK][BM];
    __shared__ float Bs[BK][BN];

    int tid = threadIdx.x;           // 0..255
    int tx = tid & 15;               // 0..15 (N dir)
    int ty = tid >> 4;               // 0..15 (M dir)
    int row0 = blockIdx.y * BM;
    int col0 = blockIdx.x * BN;

    // load mapping
    int arow = tid >> 2;             // 0..63
    int ac4  = (tid & 3) * 4;        // 0,4,8,12
    int wrow = tid >> 4;             // 0..15
    int wc4  = (tid & 15) * 4;       // 0..60

    float acc[4][4] = {};

    for (int k0 = 0; k0 < K; k0 += BK) {
        float4 a = *reinterpret_cast<const float4*>(&A[(size_t)(row0 + arow) * K + k0 + ac4]);
        if (RELU_A) {
            a.x = fmaxf(a.x, 0.f); a.y = fmaxf(a.y, 0.f);
            a.z = fmaxf(a.z, 0.f); a.w = fmaxf(a.w, 0.f);
        }
        As[ac4 + 0][arow] = a.x;
        As[ac4 + 1][arow] = a.y;
        As[ac4 + 2][arow] = a.z;
        As[ac4 + 3][arow] = a.w;

        float4 b = *reinterpret_cast<const float4*>(&W[(size_t)(k0 + wrow) * N + col0 + wc4]);
        *reinterpret_cast<float4*>(&Bs[wrow][wc4]) = b;

        __syncthreads();

        #pragma unroll
        for (int k = 0; k < BK; k++) {
            float4 ra = *reinterpret_cast<const float4*>(&As[k][ty * 4]);
            float4 rb = *reinterpret_cast<const float4*>(&Bs[k][tx * 4]);
            float raf[4] = {ra.x, ra.y, ra.z, ra.w};
            float rbf[4] = {rb.x, rb.y, rb.z, rb.w};
            #pragma unroll
            for (int i = 0; i < 4; i++)
                #pragma unroll
                for (int j = 0; j < 4; j++)
                    acc[i][j] += raf[i] * rbf[j];
        }
        __syncthreads();
    }

    #pragma unroll
    for (int i = 0; i < 4; i++) {
        int r = row0 + ty * 4 + i;
        #pragma unroll
        for (int j = 0; j < 4; j++) {
            int c = col0 + tx * 4 + j;
            float v = acc[i][j];
            if (BIAS)  v += bias[c];
            if (ACCUM) v += C[(size_t)r * N + c];
            C[(size_t)r * N + c] = v;
        }
    }
}

// ----------------------------------------------------------------------------
// Residual GLU gate: t += v * sigmoid(g)
// ----------------------------------------------------------------------------
__global__ void glu_add_kernel(float* __restrict__ t, const float* __restrict__ v,
                               const float* __restrict__ g, int n) {
    int i = blockIdx.x * blockDim.x + threadIdx.x;
    if (i >= n) return;
    float gg = g[i];
    t[i] += v[i] * (1.f / (1.f + expf(-gg)));
}

// ----------------------------------------------------------------------------
// Rational-quadratic spline + product over features.
// One block per batch row, 64 threads = one feature each.
// Matches nflows semantics: softmax -> min_bin affine -> cumsum with edge
// resets (cw[0]=0, cw[-1]=1, widths recomputed as diff), searchsorted with
// +1e-6 on the last edge, derivatives NOT scaled by 1/sqrt(H).
// ----------------------------------------------------------------------------
__device__ __forceinline__ float softplusf(float x) {
    return fmaxf(x, 0.f) + log1pf(expf(-fabsf(x)));
}

__global__ void spline_kernel(const float* __restrict__ P, const float* __restrict__ pred,
                              float* __restrict__ out) {
    int b = blockIdx.x;
    int f = threadIdx.x;   // 0..63
    const float* p = P + (size_t)b * NOUT + f * MULT_;
    float x = pred[b * F_ + f];

    float cdf;
    if (x == 1.0f) {
        cdf = 1.0f;
    } else {
        const float scale = 0.04419417382415922f;  // 1/sqrt(512)

        // widths
        float ew[NBINS];
        float mx = -1e30f;
        #pragma unroll
        for (int k = 0; k < NBINS; k++) { ew[k] = p[k] * scale; mx = fmaxf(mx, ew[k]); }
        float s = 0.f;
        #pragma unroll
        for (int k = 0; k < NBINS; k++) { ew[k] = expf(ew[k] - mx); s += ew[k]; }
        float inv = (1.f - 1e-3f * NBINS) / s;
        float cw[NBINS + 1];
        cw[0] = 0.f;
        float run = 0.f;
        #pragma unroll
        for (int k = 0; k < NBINS; k++) { run += 1e-3f + ew[k] * inv; cw[k + 1] = run; }
        cw[NBINS] = 1.f;

        // heights
        float eh[NBINS];
        mx = -1e30f;
        #pragma unroll
        for (int k = 0; k < NBINS; k++) { eh[k] = p[NBINS + k] * scale; mx = fmaxf(mx, eh[k]); }
        s = 0.f;
        #pragma unroll
        for (int k = 0; k < NBINS; k++) { eh[k] = expf(eh[k] - mx); s += eh[k]; }
        inv = (1.f - 1e-3f * NBINS) / s;
        float ch[NBINS + 1];
        ch[0] = 0.f;
        run = 0.f;
        #pragma unroll
        for (int k = 0; k < NBINS; k++) { run += 1e-3f + eh[k] * inv; ch[k + 1] = run; }
        ch[NBINS] = 1.f;

        // searchsorted: count edges <= x (last edge gets +1e-6)
        int cnt = 0;
        #pragma unroll
        for (int k = 0; k <= NBINS; k++) {
            float loc = (k == NBINS) ? (1.f + 1e-6f) : cw[k];
            cnt += (x >= loc) ? 1 : 0;
        }
        int idx = min(max(cnt - 1, 0), NBINS - 1);

        float in_cw = cw[idx], in_w = cw[idx + 1] - cw[idx];
        float in_ch = ch[idx], in_h = ch[idx + 1] - ch[idx];
        float d0 = 1e-3f + softplusf(p[2 * NBINS + idx]);
        float d1 = 1e-3f + softplusf(p[2 * NBINS + idx + 1]);

        float delta = in_h / in_w;
        float theta = (x - in_cw) / in_w;
        float tt = theta * (1.f - theta);
        float num = in_h * (delta * theta * theta + d0 * tt);
        float den = delta + (d0 + d1 - 2.f * delta) * tt;
        cdf = in_ch + num / den;
    }

    // product-reduce over 64 features (double accumulation to be robust to
    // reduction-order differences near underflow)
    double vv = (double)cdf;
    #pragma unroll
    for (int o = 16; o > 0; o >>= 1)
        vv *= __shfl_xor_sync(0xffffffffu, vv, o);

    __shared__ double sred[2];
    int w = threadIdx.x >> 5;
    if ((threadIdx.x & 31) == 0) sred[w] = vv;
    __syncthreads();
    if (threadIdx.x == 0) out[b] = (float)(sred[0] * sred[1]);
}

// ----------------------------------------------------------------------------
// Launch
// ----------------------------------------------------------------------------
extern "C" void kernel_launch(void* const* d_in, const int* in_sizes, int n_in,
                              void* d_out, int out_size) {
    const float* pred  = (const float*)d_in[0];
    const float* ctx   = (const float*)d_in[1];
    const float* W_in  = (const float*)d_in[2];
    const float* b_in  = (const float*)d_in[3];
    const float* Wc_in = (const float*)d_in[4];
    const float* bc_in = (const float*)d_in[5];
    const float* Wb1   = (const float*)d_in[6];
    const float* bb1   = (const float*)d_in[7];
    const float* Wb2   = (const float*)d_in[8];
    const float* bb2   = (const float*)d_in[9];
    const float* Wcb   = (const float*)d_in[10];
    const float* bcb   = (const float*)d_in[11];
    const float* W_out = (const float*)d_in[12];
    const float* b_out = (const float*)d_in[13];
    float* out = (float*)d_out;

    float *winm, *whhm, *woutm, *t, *u, *v, *g, *P;
    cudaGetSymbolAddress((void**)&winm,  g_WinM);
    cudaGetSymbolAddress((void**)&whhm,  g_WhhM);
    cudaGetSymbolAddress((void**)&woutm, g_WoutM);
    cudaGetSymbolAddress((void**)&t, g_t);
    cudaGetSymbolAddress((void**)&u, g_u);
    cudaGetSymbolAddress((void**)&v, g_v);
    cudaGetSymbolAddress((void**)&g, g_g);
    cudaGetSymbolAddress((void**)&P, g_P);

    const int HH = H_ * H_;

    // 1) mask weights
    mask_in_kernel <<<(F_*H_ + 255) / 256, 256>>>(W_in, winm);
    mask_hh_kernel <<<(NBLK*HH + 255) / 256, 256>>>(Wb1, whhm,            NBLK*HH);
    mask_hh_kernel <<<(NBLK*HH + 255) / 256, 256>>>(Wb2, whhm + NBLK*HH,  NBLK*HH);
    mask_out_kernel<<<(H_*NOUT + 255) / 256, 256>>>(W_out, woutm);

    // 2) t = pred @ WinM + b_in ; t += ctx @ Wc_in + bc_in
    {
        dim3 grid(H_ / BN, B_ / BM);
        sgemm_kernel<false, false, true><<<grid, 256>>>(pred, winm, b_in, t, B_, H_, F_);
        sgemm_kernel<false, true,  true><<<grid, 256>>>(ctx, Wc_in, bc_in, t, B_, H_, C_);
    }

    // 3) residual blocks
    for (int i = 0; i < NBLK; i++) {
        dim3 grid(H_ / BN, B_ / BM);
        sgemm_kernel<true,  false, true><<<grid, 256>>>(t, whhm + (size_t)i*HH,            bb1 + i*H_, u, B_, H_, H_);
        sgemm_kernel<true,  false, true><<<grid, 256>>>(u, whhm + (size_t)(NBLK + i)*HH,   bb2 + i*H_, v, B_, H_, H_);
        sgemm_kernel<false, false, true><<<grid, 256>>>(ctx, Wcb + (size_t)i*HH,           bcb + i*H_, g, B_, C_, C_);
        glu_add_kernel<<<(B_*H_ + 255) / 256, 256>>>(t, v, g, B_ * H_);
    }

    // 4) P = t @ WoutM + b_out
    {
        dim3 grid(NOUT / BN, B_ / BM);
        sgemm_kernel<false, false, true><<<grid, 256>>>(t, woutm, b_out, P, B_, NOUT, H_);
    }

    // 5) spline + product
    spline_kernel<<<B_, F_>>>(P, pred, out);
}

// round 6
// speedup vs baseline: 2.2007x; 2.2007x over previous
#include <cuda_runtime.h>
#include <cuda_bf16.h>
#include <math.h>
#include <stdint.h>

#define B_    16384
#define F_    64
#define H_    512
#define C_    512
#define NBINS 30
#define MULT_ 91
#define MP_   96
#define NOUTP (F_*MP_)     // 6144
#define KIN   (F_+C_)      // 576
#define NBLK  3
#define HH    (H_*H_)

// ---------------- device scratch ----------------
__device__ __nv_bfloat16 g_Ah[B_*KIN],  g_Al[B_*KIN];
__device__ __nv_bfloat16 g_Xh[B_*H_],   g_Xl[B_*H_];
__device__ __nv_bfloat16 g_Yh[B_*H_],   g_Yl[B_*H_];
__device__ float g_t [B_*H_];
__device__ float g_sg[B_*H_];
__device__ float g_P [(size_t)B_*NOUTP];
__device__ __nv_bfloat16 g_Wcat_h[H_*KIN],   g_Wcat_l[H_*KIN];
__device__ __nv_bfloat16 g_Whh_h[2*NBLK*HH], g_Whh_l[2*NBLK*HH];
__device__ __nv_bfloat16 g_Wcb_h[NBLK*HH],   g_Wcb_l[NBLK*HH];
__device__ __nv_bfloat16 g_Wout_h[(size_t)NOUTP*H_], g_Wout_l[(size_t)NOUTP*H_];

// ---------------- helpers ----------------
__device__ __forceinline__ uint32_t smem_u32(const void* p) {
    uint32_t a;
    asm("{ .reg .u64 t; cvta.to.shared.u64 t, %1; cvt.u32.u64 %0, t; }" : "=r"(a) : "l"(p));
    return a;
}
__device__ __forceinline__ void cp16(uint32_t dst, const void* src) {
    asm volatile("cp.async.cg.shared.global [%0], [%1], 16;" :: "r"(dst), "l"(src));
}
#define CP_COMMIT() asm volatile("cp.async.commit_group;" ::: "memory")
#define CP_WAIT(n)  asm volatile("cp.async.wait_group %0;" :: "n"(n) : "memory")

__device__ __forceinline__ void ldsm4(uint32_t& r0, uint32_t& r1, uint32_t& r2, uint32_t& r3,
                                      uint32_t addr) {
    asm volatile("ldmatrix.sync.aligned.m8n8.x4.shared.b16 {%0,%1,%2,%3}, [%4];"
                 : "=r"(r0), "=r"(r1), "=r"(r2), "=r"(r3) : "r"(addr));
}
__device__ __forceinline__ void mma16816(float* c, const uint32_t* a, const uint32_t* b) {
    asm volatile(
        "mma.sync.aligned.m16n8k16.row.col.f32.bf16.bf16.f32 "
        "{%0,%1,%2,%3}, {%4,%5,%6,%7}, {%8,%9}, {%0,%1,%2,%3};"
        : "+f"(c[0]), "+f"(c[1]), "+f"(c[2]), "+f"(c[3])
        : "r"(a[0]), "r"(a[1]), "r"(a[2]), "r"(a[3]), "r"(b[0]), "r"(b[1]));
}
__device__ __forceinline__ void split_bf16(float v, __nv_bfloat16& h, __nv_bfloat16& l) {
    h = __float2bfloat16(v);
    l = __float2bfloat16(v - __bfloat162float(h));
}

// ---------------- prep kernels (mask + transpose + hi/lo split) ----------------
// MADE degrees: d_h[j] = j % 63 + 1
__global__ void prepA(const float* __restrict__ pred, const float* __restrict__ ctx) {
    int i = blockIdx.x * blockDim.x + threadIdx.x;
    if (i >= B_*KIN) return;
    int r = i / KIN, c = i % KIN;
    float v = (c < F_) ? pred[r*F_ + c] : ctx[r*C_ + (c - F_)];
    split_bf16(v, g_Ah[i], g_Al[i]);
}
__global__ void prepWcat(const float* __restrict__ W_in, const float* __restrict__ Wc_in) {
    int i = blockIdx.x * blockDim.x + threadIdx.x;
    if (i >= H_*KIN) return;
    int n = i / KIN, k = i % KIN;
    float v;
    if (k < F_) { v = W_in[k*H_ + n]; if (!((n % 63) + 1 >= k + 1)) v = 0.f; }
    else        { v = Wc_in[(k - F_)*H_ + n]; }
    split_bf16(v, g_Wcat_h[i], g_Wcat_l[i]);
}
__global__ void prepWhh(const float* __restrict__ Wb1, const float* __restrict__ Wb2) {
    int i = blockIdx.x * blockDim.x + threadIdx.x;
    if (i >= 2*NBLK*HH) return;
    int mat = i / HH, rem = i % HH;
    int n = rem / H_, k = rem % H_;
    const float* W = (mat < NBLK) ? (Wb1 + (size_t)mat*HH) : (Wb2 + (size_t)(mat - NBLK)*HH);
    float v = W[k*H_ + n];
    if ((n % 63) < (k % 63)) v = 0.f;
    split_bf16(v, g_Whh_h[i], g_Whh_l[i]);
}
__global__ void prepWcb(const float* __restrict__ Wcb) {
    int i = blockIdx.x * blockDim.x + threadIdx.x;
    if (i >= NBLK*HH) return;
    int mat = i / HH, rem = i % HH;
    int n = rem / H_, k = rem % H_;
    float v = Wcb[(size_t)mat*HH + k*H_ + n];
    split_bf16(v, g_Wcb_h[i], g_Wcb_l[i]);
}
__global__ void prepWout(const float* __restrict__ W_out) {
    size_t i = (size_t)blockIdx.x * blockDim.x + threadIdx.x;
    if (i >= (size_t)NOUTP*H_) return;
    int n = (int)(i / H_), k = (int)(i % H_);
    int f = n / MP_, j = n % MP_;
    float v = 0.f;
    if (j < MULT_ && f > (k % 63)) v = W_out[(size_t)k*(F_*MULT_) + f*MULT_ + j];
    split_bf16(v, g_Wout_h[i], g_Wout_l[i]);
}

// ---------------- bf16x3 mma.sync GEMM, fused epilogues ----------------
// D[128 x 128] = (Ah+Al)[128 x K] @ (Bh+Bl)[128 x K]^T  (drop lo*lo)
// EPI: 0=t-init  1=relu split  2=sigmoid  3=GLU residual  4=P write
#define BM 128
#define BN 128
#define BK 32
#define NSTAGE 3
#define ROWB 80                       // 64 B row + 16 B pad: conflict-free ldmatrix
#define OFF_AH 0
#define OFF_AL 10240
#define OFF_BH 20480
#define OFF_BL 30720
#define STAGE_B 40960
#define SMEM_SZ (NSTAGE*STAGE_B)      // 122880

__device__ __forceinline__ void issue_stage(
    uint32_t sb, const __nv_bfloat16* Ah, const __nv_bfloat16* Al, int lda,
    const __nv_bfloat16* Bh, const __nv_bfloat16* Bl, int ldb,
    int m0, int n0, int k0, int tid)
{
    #pragma unroll
    for (int it = 0; it < 2; it++) {
        int i = tid + it * 256;
        int r = i >> 2;
        int c16 = (i & 3) * 16;         // byte offset within row
        int ce  = (i & 3) * 8;          // element offset
        cp16(sb + OFF_AH + r*ROWB + c16, Ah + (size_t)(m0 + r) * lda + k0 + ce);
        cp16(sb + OFF_AL + r*ROWB + c16, Al + (size_t)(m0 + r) * lda + k0 + ce);
        cp16(sb + OFF_BH + r*ROWB + c16, Bh + (size_t)(n0 + r) * ldb + k0 + ce);
        cp16(sb + OFF_BL + r*ROWB + c16, Bl + (size_t)(n0 + r) * ldb + k0 + ce);
    }
}

template<int EPI, bool RELUF, bool WRITET>
__device__ __forceinline__ void epi_pair(
    float v0, float v1, int gr, int gc,
    const float* __restrict__ bias1, const float* __restrict__ bias2,
    float* __restrict__ tbuf, float* __restrict__ sgbuf, float* __restrict__ outF,
    __nv_bfloat16* __restrict__ outH, __nv_bfloat16* __restrict__ outL)
{
    if (EPI == 0) {
        v0 += bias1[gc] + bias2[gc];
        v1 += bias1[gc+1] + bias2[gc+1];
        int g = gr * H_ + gc;
        *reinterpret_cast<float2*>(&tbuf[g]) = make_float2(v0, v1);
        float z0 = fmaxf(v0, 0.f), z1 = fmaxf(v1, 0.f);
        __nv_bfloat162 hv, lv;
        split_bf16(z0, hv.x, lv.x); split_bf16(z1, hv.y, lv.y);
        *reinterpret_cast<__nv_bfloat162*>(&outH[g]) = hv;
        *reinterpret_cast<__nv_bfloat162*>(&outL[g]) = lv;
    } else if (EPI == 1) {
        v0 += bias1[gc]; v1 += bias1[gc+1];
        int g = gr * H_ + gc;
        float z0 = fmaxf(v0, 0.f), z1 = fmaxf(v1, 0.f);
        __nv_bfloat162 hv, lv;
        split_bf16(z0, hv.x, lv.x); split_bf16(z1, hv.y, lv.y);
        *reinterpret_cast<__nv_bfloat162*>(&outH[g]) = hv;
        *reinterpret_cast<__nv_bfloat162*>(&outL[g]) = lv;
    } else if (EPI == 2) {
        v0 += bias1[gc]; v1 += bias1[gc+1];
        int g = gr * H_ + gc;
        float s0 = 1.f / (1.f + expf(-v0)), s1 = 1.f / (1.f + expf(-v1));
        *reinterpret_cast<float2*>(&sgbuf[g]) = make_float2(s0, s1);
    } else if (EPI == 3) {
        v0 += bias1[gc]; v1 += bias1[gc+1];
        int g = gr * H_ + gc;
        float2 tv = *reinterpret_cast<const float2*>(&tbuf[g]);
        float2 sv = *reinterpret_cast<const float2*>(&sgbuf[g]);
        float t0 = tv.x + v0 * sv.x, t1 = tv.y + v1 * sv.y;
        if (WRITET) *reinterpret_cast<float2*>(&tbuf[g]) = make_float2(t0, t1);
        float z0 = RELUF ? fmaxf(t0, 0.f) : t0;
        float z1 = RELUF ? fmaxf(t1, 0.f) : t1;
        __nv_bfloat162 hv, lv;
        split_bf16(z0, hv.x, lv.x); split_bf16(z1, hv.y, lv.y);
        *reinterpret_cast<__nv_bfloat162*>(&outH[g]) = hv;
        *reinterpret_cast<__nv_bfloat162*>(&outL[g]) = lv;
    } else {  // EPI == 4: P write (padded cols j>=91 carry zeros)
        int f = gc / MP_, j0 = gc - f * MP_;
        if (j0 < MULT_)     v0 += bias1[f * MULT_ + j0];
        if (j0 + 1 < MULT_) v1 += bias1[f * MULT_ + j0 + 1];
        *reinterpret_cast<float2*>(&outF[(size_t)gr * NOUTP + gc]) = make_float2(v0, v1);
    }
}

template<int EPI, bool RELUF, bool WRITET>
__global__ void __launch_bounds__(256, 1) gemm_bf3(
    const __nv_bfloat16* __restrict__ Ah, const __nv_bfloat16* __restrict__ Al, int lda,
    const __nv_bfloat16* __restrict__ Bh, const __nv_bfloat16* __restrict__ Bl, int K,
    const float* __restrict__ bias1, const float* __restrict__ bias2,
    float* __restrict__ tbuf, float* __restrict__ sgbuf,
    float* __restrict__ outF,
    __nv_bfloat16* __restrict__ outH, __nv_bfloat16* __restrict__ outL)
{
    extern __shared__ char smem[];
    uint32_t sbase = smem_u32(smem);
    int tid = threadIdx.x;
    int lane = tid & 31, wid = tid >> 5;
    int wm = (wid >> 1) * 32;           // warp row offset (4 warps in M)
    int wn = (wid & 1) * 64;            // warp col offset (2 warps in N)
    int m0 = blockIdx.y * BM, n0 = blockIdx.x * BN;

    float acc[2][8][4];
    #pragma unroll
    for (int mt = 0; mt < 2; mt++)
        #pragma unroll
        for (int nt = 0; nt < 8; nt++)
            #pragma unroll
            for (int q = 0; q < 4; q++) acc[mt][nt][q] = 0.f;

    const int kiters = K / BK;

    #pragma unroll
    for (int s = 0; s < NSTAGE - 1; s++) {
        if (s < kiters)
            issue_stage(sbase + s*STAGE_B, Ah, Al, lda, Bh, Bl, K, m0, n0, s*BK, tid);
        CP_COMMIT();
    }

    int a_row = (lane & 15);
    uint32_t a_colb = (lane >> 4) * 16;
    int b_row = ((lane >> 4) << 3) + (lane & 7);
    uint32_t b_colb = ((lane >> 3) & 1) * 16;

    for (int ki = 0; ki < kiters; ki++) {
        CP_WAIT(NSTAGE - 2);
        __syncthreads();

        int kn = ki + NSTAGE - 1;
        if (kn < kiters)
            issue_stage(sbase + (kn % NSTAGE)*STAGE_B, Ah, Al, lda, Bh, Bl, K,
                        m0, n0, kn*BK, tid);
        CP_COMMIT();

        uint32_t sb = sbase + (ki % NSTAGE) * STAGE_B;
        #pragma unroll
        for (int ks = 0; ks < 2; ks++) {
            uint32_t kb = ks * 32;
            uint32_t ah[2][4], al[2][4];
            #pragma unroll
            for (int mt = 0; mt < 2; mt++) {
                uint32_t ar = (uint32_t)(wm + mt*16 + a_row) * ROWB + kb + a_colb;
                ldsm4(ah[mt][0], ah[mt][1], ah[mt][2], ah[mt][3], sb + OFF_AH + ar);
                ldsm4(al[mt][0], al[mt][1], al[mt][2], al[mt][3], sb + OFF_AL + ar);
            }
            uint32_t bh[8][2], bl[8][2];
            #pragma unroll
            for (int bt = 0; bt < 4; bt++) {
                uint32_t br = (uint32_t)(wn + bt*16 + b_row) * ROWB + kb + b_colb;
                ldsm4(bh[2*bt][0], bh[2*bt][1], bh[2*bt+1][0], bh[2*bt+1][1], sb + OFF_BH + br);
                ldsm4(bl[2*bt][0], bl[2*bt][1], bl[2*bt+1][0], bl[2*bt+1][1], sb + OFF_BL + br);
            }
            #pragma unroll
            for (int mt = 0; mt < 2; mt++)
                #pragma unroll
                for (int nt = 0; nt < 8; nt++) {
                    mma16816(acc[mt][nt], ah[mt], bh[nt]);   // hi*hi
                    mma16816(acc[mt][nt], al[mt], bh[nt]);   // lo*hi
                    mma16816(acc[mt][nt], ah[mt], bl[nt]);   // hi*lo
                }
        }
        __syncthreads();
    }

    #pragma unroll
    for (int mt = 0; mt < 2; mt++)
        #pragma unroll
        for (int nt = 0; nt < 8; nt++) {
            int gr = m0 + wm + mt*16 + (lane >> 2);
            int gc = n0 + wn + nt*8 + (lane & 3) * 2;
            epi_pair<EPI,RELUF,WRITET>(acc[mt][nt][0], acc[mt][nt][1], gr,     gc,
                                       bias1, bias2, tbuf, sgbuf, outF, outH, outL);
            epi_pair<EPI,RELUF,WRITET>(acc[mt][nt][2], acc[mt][nt][3], gr + 8, gc,
                                       bias1, bias2, tbuf, sgbuf, outF, outH, outL);
        }
}

// ---------------- RQ spline + feature product ----------------
__device__ __forceinline__ float softplusf(float x) {
    return fmaxf(x, 0.f) + log1pf(expf(-fabsf(x)));
}

__global__ void spline_kernel(const float* __restrict__ P, const float* __restrict__ pred,
                              float* __restrict__ out) {
    int b = blockIdx.x;
    int f = threadIdx.x;
    const float* p = P + (size_t)b * NOUTP + f * MP_;
    float x = pred[b * F_ + f];

    float cdf;
    if (x == 1.0f) {
        cdf = 1.0f;
    } else {
        const float scale = 0.04419417382415922f;  // 1/sqrt(512)
        float ew[NBINS], mx = -1e30f;
        #pragma unroll
        for (int k = 0; k < NBINS; k++) { ew[k] = p[k] * scale; mx = fmaxf(mx, ew[k]); }
        float s = 0.f;
        #pragma unroll
        for (int k = 0; k < NBINS; k++) { ew[k] = expf(ew[k] - mx); s += ew[k]; }
        float inv = (1.f - 1e-3f * NBINS) / s;
        float cw[NBINS + 1];
        cw[0] = 0.f;
        float run = 0.f;
        #pragma unroll
        for (int k = 0; k < NBINS; k++) { run += 1e-3f + ew[k] * inv; cw[k + 1] = run; }
        cw[NBINS] = 1.f;

        float eh[NBINS];
        mx = -1e30f;
        #pragma unroll
        for (int k = 0; k < NBINS; k++) { eh[k] = p[NBINS + k] * scale; mx = fmaxf(mx, eh[k]); }
        s = 0.f;
        #pragma unroll
        for (int k = 0; k < NBINS; k++) { eh[k] = expf(eh[k] - mx); s += eh[k]; }
        inv = (1.f - 1e-3f * NBINS) / s;
        float ch[NBINS + 1];
        ch[0] = 0.f;
        run = 0.f;
        #pragma unroll
        for (int k = 0; k < NBINS; k++) { run += 1e-3f + eh[k] * inv; ch[k + 1] = run; }
        ch[NBINS] = 1.f;

        int cnt = 0;
        #pragma unroll
        for (int k = 0; k <= NBINS; k++) {
            float loc = (k == NBINS) ? (1.f + 1e-6f) : cw[k];
            cnt += (x >= loc) ? 1 : 0;
        }
        int idx = min(max(cnt - 1, 0), NBINS - 1);

        float in_cw = cw[idx], in_w = cw[idx + 1] - cw[idx];
        float in_ch = ch[idx], in_h = ch[idx + 1] - ch[idx];
        float d0 = 1e-3f + softplusf(p[2 * NBINS + idx]);
        float d1 = 1e-3f + softplusf(p[2 * NBINS + idx + 1]);

        float delta = in_h / in_w;
        float theta = (x - in_cw) / in_w;
        float tt = theta * (1.f - theta);
        float num = in_h * (delta * theta * theta + d0 * tt);
        float den = delta + (d0 + d1 - 2.f * delta) * tt;
        cdf = in_ch + num / den;
    }

    double vv = (double)cdf;
    #pragma unroll
    for (int o = 16; o > 0; o >>= 1)
        vv *= __shfl_xor_sync(0xffffffffu, vv, o);

    __shared__ double sred[2];
    int w = threadIdx.x >> 5;
    if ((threadIdx.x & 31) == 0) sred[w] = vv;
    __syncthreads();
    if (threadIdx.x == 0) out[b] = (float)(sred[0] * sred[1]);
}

// ---------------- launch ----------------
extern "C" void kernel_launch(void* const* d_in, const int* in_sizes, int n_in,
                              void* d_out, int out_size) {
    const float* pred  = (const float*)d_in[0];
    const float* ctx   = (const float*)d_in[1];
    const float* W_in  = (const float*)d_in[2];
    const float* b_in  = (const float*)d_in[3];
    const float* Wc_in = (const float*)d_in[4];
    const float* bc_in = (const float*)d_in[5];
    const float* Wb1   = (const float*)d_in[6];
    const float* bb1   = (const float*)d_in[7];
    const float* Wb2   = (const float*)d_in[8];
    const float* bb2   = (const float*)d_in[9];
    const float* Wcb   = (const float*)d_in[10];
    const float* bcb   = (const float*)d_in[11];
    const float* W_out = (const float*)d_in[12];
    const float* b_out = (const float*)d_in[13];
    float* out = (float*)d_out;

    cudaFuncSetAttribute(gemm_bf3<0,false,false>, cudaFuncAttributeMaxDynamicSharedMemorySize, SMEM_SZ);
    cudaFuncSetAttribute(gemm_bf3<1,false,false>, cudaFuncAttributeMaxDynamicSharedMemorySize, SMEM_SZ);
    cudaFuncSetAttribute(gemm_bf3<2,false,false>, cudaFuncAttributeMaxDynamicSharedMemorySize, SMEM_SZ);
    cudaFuncSetAttribute(gemm_bf3<3,true, true >, cudaFuncAttributeMaxDynamicSharedMemorySize, SMEM_SZ);
    cudaFuncSetAttribute(gemm_bf3<3,false,true >, cudaFuncAttributeMaxDynamicSharedMemorySize, SMEM_SZ);
    cudaFuncSetAttribute(gemm_bf3<4,false,false>, cudaFuncAttributeMaxDynamicSharedMemorySize, SMEM_SZ);

    __nv_bfloat16 *Ah, *Al, *Xh, *Xl, *Yh, *Yl;
    __nv_bfloat16 *Wch, *Wcl, *Whh, *Whl, *Wbh, *Wbl, *Woh, *Wol;
    float *t, *sg, *P;
    cudaGetSymbolAddress((void**)&Ah, g_Ah);   cudaGetSymbolAddress((void**)&Al, g_Al);
    cudaGetSymbolAddress((void**)&Xh, g_Xh);   cudaGetSymbolAddress((void**)&Xl, g_Xl);
    cudaGetSymbolAddress((void**)&Yh, g_Yh);   cudaGetSymbolAddress((void**)&Yl, g_Yl);
    cudaGetSymbolAddress((void**)&Wch, g_Wcat_h); cudaGetSymbolAddress((void**)&Wcl, g_Wcat_l);
    cudaGetSymbolAddress((void**)&Whh, g_Whh_h);  cudaGetSymbolAddress((void**)&Whl, g_Whh_l);
    cudaGetSymbolAddress((void**)&Wbh, g_Wcb_h);  cudaGetSymbolAddress((void**)&Wbl, g_Wcb_l);
    cudaGetSymbolAddress((void**)&Woh, g_Wout_h); cudaGetSymbolAddress((void**)&Wol, g_Wout_l);
    cudaGetSymbolAddress((void**)&t, g_t);
    cudaGetSymbolAddress((void**)&sg, g_sg);
    cudaGetSymbolAddress((void**)&P, g_P);

    // 1) preps
    prepA   <<<(B_*KIN + 255) / 256, 256>>>(pred, ctx);
    prepWcat<<<(H_*KIN + 255) / 256, 256>>>(W_in, Wc_in);
    prepWhh <<<(2*NBLK*HH + 255) / 256, 256>>>(Wb1, Wb2);
    prepWcb <<<(NBLK*HH + 255) / 256, 256>>>(Wcb);
    prepWout<<<((int)(((size_t)NOUTP*H_ + 255) / 256)), 256>>>(W_out);

    dim3 gH(H_ / BN, B_ / BM);   // (4, 128)

    // 2) t = [pred|ctx] @ Wcat + b_in + bc_in ; X = split(relu(t)); tbuf = t
    gemm_bf3<0,false,false><<<gH, 256, SMEM_SZ>>>(Ah, Al, KIN, Wch, Wcl, KIN,
        b_in, bc_in, t, nullptr, nullptr, Xh, Xl);

    // 3) residual blocks
    for (int i = 0; i < NBLK; i++) {
        gemm_bf3<1,false,false><<<gH, 256, SMEM_SZ>>>(Xh, Xl, H_,
            Whh + (size_t)i*HH, Whl + (size_t)i*HH, H_,
            bb1 + i*H_, nullptr, nullptr, nullptr, nullptr, Yh, Yl);
        gemm_bf3<2,false,false><<<gH, 256, SMEM_SZ>>>(Ah + F_, Al + F_, KIN,
            Wbh + (size_t)i*HH, Wbl + (size_t)i*HH, C_,
            bcb + i*H_, nullptr, nullptr, sg, nullptr, nullptr, nullptr);
        if (i < NBLK - 1)
            gemm_bf3<3,true,true><<<gH, 256, SMEM_SZ>>>(Yh, Yl, H_,
                Whh + (size_t)(NBLK + i)*HH, Whl + (size_t)(NBLK + i)*HH, H_,
                bb2 + i*H_, nullptr, t, sg, nullptr, Xh, Xl);
        else
            gemm_bf3<3,false,true><<<gH, 256, SMEM_SZ>>>(Yh, Yl, H_,
                Whh + (size_t)(NBLK + i)*HH, Whl + (size_t)(NBLK + i)*HH, H_,
                bb2 + i*H_, nullptr, t, sg, nullptr, Xh, Xl);
    }

    // 4) P = t @ WoutM + b_out (padded N = 6144)
    dim3 gO(NOUTP / BN, B_ / BM);  // (48, 128)
    gemm_bf3<4,false,false><<<gO, 256, SMEM_SZ>>>(Xh, Xl, H_, Woh, Wol, H_,
        b_out, nullptr, nullptr, nullptr, P, nullptr, nullptr);

    // 5) spline + product
    spline_kernel<<<B_, F_>>>(P, pred, out);
}

// round 8
// speedup vs baseline: 2.8502x; 1.2951x over previous
#include <cuda_runtime.h>
#include <cuda_bf16.h>
#include <math.h>
#include <stdint.h>

#define B_    16384
#define F_    64
#define H_    512
#define C_    512
#define NBINS 30
#define MULT_ 91
#define MP_   96
#define NOUTP (F_*MP_)     // 6144
#define KIN   (F_+C_)      // 576
#define NBLK  3
#define HH    (H_*H_)

// ---------------- device scratch ----------------
__device__ __nv_bfloat16 g_Ah[B_*KIN],  g_Al[B_*KIN];
__device__ __nv_bfloat16 g_Xh[B_*H_],   g_Xl[B_*H_];
__device__ __nv_bfloat16 g_Yh[B_*H_],   g_Yl[B_*H_];
__device__ float g_t [B_*H_];
__device__ float g_sg[B_*H_];
__device__ float g_P [(size_t)B_*NOUTP];
__device__ float g_pb[10*H_];                       // permuted biases
__device__ __nv_bfloat16 g_Wcat_h[H_*KIN],   g_Wcat_l[H_*KIN];
__device__ __nv_bfloat16 g_Whh_h[2*NBLK*HH], g_Whh_l[2*NBLK*HH];
__device__ __nv_bfloat16 g_Wcb_h[NBLK*HH],   g_Wcb_l[NBLK*HH];
__device__ __nv_bfloat16 g_Wout_h[(size_t)NOUTP*H_], g_Wout_l[(size_t)NOUTP*H_];

// ---------------- degree-sort permutation (MADE degrees d(j)=j%63+1) ----------------
// sorted position s -> degree deg(s); cum(d) = #units with degree <= d = 8d + min(d,8)
__host__ __device__ __forceinline__ int deg_s(int s)  { return (s < 72) ? s / 9 + 1 : s / 8; }
__host__ __device__ __forceinline__ int cum_d(int d)  { return 8 * d + (d < 8 ? d : 8); }
__host__ __device__ __forceinline__ int perm_s(int s) {
    int d = deg_s(s);
    int r = (s < 72) ? s % 9 : (s & 7);
    return (d - 1) + 63 * r;
}

// ---------------- helpers ----------------
__device__ __forceinline__ uint32_t smem_u32(const void* p) {
    uint32_t a;
    asm("{ .reg .u64 t; cvta.to.shared.u64 t, %1; cvt.u32.u64 %0, t; }" : "=r"(a) : "l"(p));
    return a;
}
__device__ __forceinline__ void cp16(uint32_t dst, const void* src) {
    asm volatile("cp.async.cg.shared.global [%0], [%1], 16;" :: "r"(dst), "l"(src));
}
#define CP_COMMIT() asm volatile("cp.async.commit_group;" ::: "memory")
#define CP_WAIT(n)  asm volatile("cp.async.wait_group %0;" :: "n"(n) : "memory")

__device__ __forceinline__ void ldsm4(uint32_t& r0, uint32_t& r1, uint32_t& r2, uint32_t& r3,
                                      uint32_t addr) {
    asm volatile("ldmatrix.sync.aligned.m8n8.x4.shared.b16 {%0,%1,%2,%3}, [%4];"
                 : "=r"(r0), "=r"(r1), "=r"(r2), "=r"(r3) : "r"(addr));
}
__device__ __forceinline__ void mma16816(float* c, const uint32_t* a, const uint32_t* b) {
    asm volatile(
        "mma.sync.aligned.m16n8k16.row.col.f32.bf16.bf16.f32 "
        "{%0,%1,%2,%3}, {%4,%5,%6,%7}, {%8,%9}, {%0,%1,%2,%3};"
        : "+f"(c[0]), "+f"(c[1]), "+f"(c[2]), "+f"(c[3])
        : "r"(a[0]), "r"(a[1]), "r"(a[2]), "r"(a[3]), "r"(b[0]), "r"(b[1]));
}
__device__ __forceinline__ void split_bf16(float v, __nv_bfloat16& h, __nv_bfloat16& l) {
    h = __float2bfloat16(v);
    l = __float2bfloat16(v - __bfloat162float(h));
}

// ---------------- prep kernels (mask + permute + transpose + hi/lo split) ----------------
__global__ void prepA(const float* __restrict__ pred, const float* __restrict__ ctx) {
    int i = blockIdx.x * blockDim.x + threadIdx.x;
    if (i >= B_*KIN) return;
    int r = i / KIN, c = i % KIN;
    float v = (c < F_) ? pred[r*F_ + c] : ctx[r*C_ + (c - F_)];
    split_bf16(v, g_Ah[i], g_Al[i]);
}
__global__ void prepWcat(const float* __restrict__ W_in, const float* __restrict__ Wc_in) {
    int i = blockIdx.x * blockDim.x + threadIdx.x;
    if (i >= H_*KIN) return;
    int n = i / KIN, k = i % KIN;
    int no = perm_s(n), dn = deg_s(n);
    float v;
    if (k < F_) { v = (dn >= k + 1) ? W_in[k*H_ + no] : 0.f; }
    else        { v = Wc_in[(k - F_)*H_ + no]; }
    split_bf16(v, g_Wcat_h[i], g_Wcat_l[i]);
}
__global__ void prepWhh(const float* __restrict__ Wb1, const float* __restrict__ Wb2) {
    int i = blockIdx.x * blockDim.x + threadIdx.x;
    if (i >= 2*NBLK*HH) return;
    int mat = i / HH, rem = i % HH;
    int n = rem / H_, k = rem % H_;                 // n = sorted out, k = sorted in
    const float* W = (mat < NBLK) ? (Wb1 + (size_t)mat*HH) : (Wb2 + (size_t)(mat - NBLK)*HH);
    float v = (deg_s(k) <= deg_s(n)) ? W[perm_s(k)*H_ + perm_s(n)] : 0.f;
    split_bf16(v, g_Whh_h[i], g_Whh_l[i]);
}
__global__ void prepWcb(const float* __restrict__ Wcb) {
    int i = blockIdx.x * blockDim.x + threadIdx.x;
    if (i >= NBLK*HH) return;
    int mat = i / HH, rem = i % HH;
    int n = rem / H_, k = rem % H_;                 // n = sorted out, k = ctx (dense)
    float v = Wcb[(size_t)mat*HH + k*H_ + perm_s(n)];
    split_bf16(v, g_Wcb_h[i], g_Wcb_l[i]);
}
__global__ void prepWout(const float* __restrict__ W_out) {
    size_t i = (size_t)blockIdx.x * blockDim.x + threadIdx.x;
    if (i >= (size_t)NOUTP*H_) return;
    int n = (int)(i / H_), k = (int)(i % H_);       // n = feature col, k = sorted hidden
    int f = n / MP_, j = n % MP_;
    float v = 0.f;
    if (j < MULT_ && f >= deg_s(k)) v = W_out[(size_t)perm_s(k)*(F_*MULT_) + f*MULT_ + j];
    split_bf16(v, g_Wout_h[i], g_Wout_l[i]);
}
__global__ void permB(const float* __restrict__ b_in, const float* __restrict__ bc_in,
                      const float* __restrict__ bb1, const float* __restrict__ bb2,
                      const float* __restrict__ bcb) {
    int i = blockIdx.x * blockDim.x + threadIdx.x;
    if (i >= 10*H_) return;
    int v = i / H_, s = i % H_, j = perm_s(s);
    float x;
    if      (v == 0) x = b_in[j] + bc_in[j];
    else if (v <= 3) x = bb1[(v-1)*H_ + j];
    else if (v <= 6) x = bb2[(v-4)*H_ + j];
    else             x = bcb[(v-7)*H_ + j];
    g_pb[i] = x;
}

// ---------------- bf16x3 mma.sync GEMM, degree-limited K, fused epilogues ----------------
// KMODE: 0=full K   1=HH (N = sorted hidden)   2=out (N = feature cols)
#define BM 128
#define BN 128
#define BK 32
#define NSTAGE 3
#define ROWB 80
#define OFF_AH 0
#define OFF_AL 10240
#define OFF_BH 20480
#define OFF_BL 30720
#define STAGE_B 40960
#define SMEM_SZ (NSTAGE*STAGE_B)

__device__ __forceinline__ void issue_stage(
    uint32_t sb, const __nv_bfloat16* Ah, const __nv_bfloat16* Al, int lda,
    const __nv_bfloat16* Bh, const __nv_bfloat16* Bl, int ldb,
    int m0, int n0, int k0, int tid)
{
    #pragma unroll
    for (int it = 0; it < 2; it++) {
        int i = tid + it * 256;
        int r = i >> 2;
        int c16 = (i & 3) * 16;
        int ce  = (i & 3) * 8;
        cp16(sb + OFF_AH + r*ROWB + c16, Ah + (size_t)(m0 + r) * lda + k0 + ce);
        cp16(sb + OFF_AL + r*ROWB + c16, Al + (size_t)(m0 + r) * lda + k0 + ce);
        cp16(sb + OFF_BH + r*ROWB + c16, Bh + (size_t)(n0 + r) * ldb + k0 + ce);
        cp16(sb + OFF_BL + r*ROWB + c16, Bl + (size_t)(n0 + r) * ldb + k0 + ce);
    }
}

template<int EPI, bool RELUF, bool WRITET>
__device__ __forceinline__ void epi_pair(
    float v0, float v1, int gr, int gc,
    const float* __restrict__ bias1,
    float* __restrict__ tbuf, float* __restrict__ sgbuf, float* __restrict__ outF,
    __nv_bfloat16* __restrict__ outH, __nv_bfloat16* __restrict__ outL)
{
    if (EPI == 0) {
        v0 += bias1[gc]; v1 += bias1[gc+1];
        int g = gr * H_ + gc;
        *reinterpret_cast<float2*>(&tbuf[g]) = make_float2(v0, v1);
        float z0 = fmaxf(v0, 0.f), z1 = fmaxf(v1, 0.f);
        __nv_bfloat162 hv, lv;
        split_bf16(z0, hv.x, lv.x); split_bf16(z1, hv.y, lv.y);
        *reinterpret_cast<__nv_bfloat162*>(&outH[g]) = hv;
        *reinterpret_cast<__nv_bfloat162*>(&outL[g]) = lv;
    } else if (EPI == 1) {
        v0 += bias1[gc]; v1 += bias1[gc+1];
        int g = gr * H_ + gc;
        float z0 = fmaxf(v0, 0.f), z1 = fmaxf(v1, 0.f);
        __nv_bfloat162 hv, lv;
        split_bf16(z0, hv.x, lv.x); split_bf16(z1, hv.y, lv.y);
        *reinterpret_cast<__nv_bfloat162*>(&outH[g]) = hv;
        *reinterpret_cast<__nv_bfloat162*>(&outL[g]) = lv;
    } else if (EPI == 2) {
        v0 += bias1[gc]; v1 += bias1[gc+1];
        int g = gr * H_ + gc;
        float s0 = 1.f / (1.f + expf(-v0)), s1 = 1.f / (1.f + expf(-v1));
        *reinterpret_cast<float2*>(&sgbuf[g]) = make_float2(s0, s1);
    } else if (EPI == 3) {
        v0 += bias1[gc]; v1 += bias1[gc+1];
        int g = gr * H_ + gc;
        float2 tv = *reinterpret_cast<const float2*>(&tbuf[g]);
        float2 sv = *reinterpret_cast<const float2*>(&sgbuf[g]);
        float t0 = tv.x + v0 * sv.x, t1 = tv.y + v1 * sv.y;
        if (WRITET) *reinterpret_cast<float2*>(&tbuf[g]) = make_float2(t0, t1);
        float z0 = RELUF ? fmaxf(t0, 0.f) : t0;
        float z1 = RELUF ? fmaxf(t1, 0.f) : t1;
        __nv_bfloat162 hv, lv;
        split_bf16(z0, hv.x, lv.x); split_bf16(z1, hv.y, lv.y);
        *reinterpret_cast<__nv_bfloat162*>(&outH[g]) = hv;
        *reinterpret_cast<__nv_bfloat162*>(&outL[g]) = lv;
    } else {  // EPI == 4
        int f = gc / MP_, j0 = gc - f * MP_;
        if (j0 < MULT_)     v0 += bias1[f * MULT_ + j0];
        if (j0 + 1 < MULT_) v1 += bias1[f * MULT_ + j0 + 1];
        *reinterpret_cast<float2*>(&outF[(size_t)gr * NOUTP + gc]) = make_float2(v0, v1);
    }
}

template<int EPI, bool RELUF, bool WRITET, int KMODE>
__global__ void __launch_bounds__(256, 1) gemm_bf3(
    const __nv_bfloat16* __restrict__ Ah, const __nv_bfloat16* __restrict__ Al, int lda,
    const __nv_bfloat16* __restrict__ Bh, const __nv_bfloat16* __restrict__ Bl, int K,
    const float* __restrict__ bias1,
    float* __restrict__ tbuf, float* __restrict__ sgbuf,
    float* __restrict__ outF,
    __nv_bfloat16* __restrict__ outH, __nv_bfloat16* __restrict__ outL)
{
    extern __shared__ char smem[];
    uint32_t sbase = smem_u32(smem);
    int tid = threadIdx.x;
    int lane = tid & 31, wid = tid >> 5;
    int wm = (wid >> 1) * 32;
    int wn = (wid & 1) * 64;
    int m0 = blockIdx.y * BM, n0 = blockIdx.x * BN;

    // degree-limited K (skipped rows are exact zeros in the sorted weights)
    int klim = K;
    if (KMODE == 1) {
        int dmax = deg_s(n0 + BN - 1);
        klim = min(K, (cum_d(dmax) + BK - 1) & ~(BK - 1));
    } else if (KMODE == 2) {
        int T = (n0 + BN - 1) / MP_;
        if (T > 63) T = 63;
        klim = min(K, (cum_d(T) + BK - 1) & ~(BK - 1));
    }
    const int kiters = klim / BK;

    float acc[2][8][4];
    #pragma unroll
    for (int mt = 0; mt < 2; mt++)
        #pragma unroll
        for (int nt = 0; nt < 8; nt++)
            #pragma unroll
            for (int q = 0; q < 4; q++) acc[mt][nt][q] = 0.f;

    #pragma unroll
    for (int s = 0; s < NSTAGE - 1; s++) {
        if (s < kiters)
            issue_stage(sbase + s*STAGE_B, Ah, Al, lda, Bh, Bl, K, m0, n0, s*BK, tid);
        CP_COMMIT();
    }

    int a_row = (lane & 15);
    uint32_t a_colb = (lane >> 4) * 16;
    int b_row = ((lane >> 4) << 3) + (lane & 7);
    uint32_t b_colb = ((lane >> 3) & 1) * 16;

    for (int ki = 0; ki < kiters; ki++) {
        CP_WAIT(NSTAGE - 2);
        __syncthreads();

        int kn = ki + NSTAGE - 1;
        if (kn < kiters)
            issue_stage(sbase + (kn % NSTAGE)*STAGE_B, Ah, Al, lda, Bh, Bl, K,
                        m0, n0, kn*BK, tid);
        CP_COMMIT();

        uint32_t sb = sbase + (ki % NSTAGE) * STAGE_B;
        #pragma unroll
        for (int ks = 0; ks < 2; ks++) {
            uint32_t kb = ks * 32;
            uint32_t ah[2][4], al[2][4];
            #pragma unroll
            for (int mt = 0; mt < 2; mt++) {
                uint32_t ar = (uint32_t)(wm + mt*16 + a_row) * ROWB + kb + a_colb;
                ldsm4(ah[mt][0], ah[mt][1], ah[mt][2], ah[mt][3], sb + OFF_AH + ar);
                ldsm4(al[mt][0], al[mt][1], al[mt][2], al[mt][3], sb + OFF_AL + ar);
            }
            uint32_t bh[8][2], bl[8][2];
            #pragma unroll
            for (int bt = 0; bt < 4; bt++) {
                uint32_t br = (uint32_t)(wn + bt*16 + b_row) * ROWB + kb + b_colb;
                ldsm4(bh[2*bt][0], bh[2*bt][1], bh[2*bt+1][0], bh[2*bt+1][1], sb + OFF_BH + br);
                ldsm4(bl[2*bt][0], bl[2*bt][1], bl[2*bt+1][0], bl[2*bt+1][1], sb + OFF_BL + br);
            }
            #pragma unroll
            for (int mt = 0; mt < 2; mt++)
                #pragma unroll
                for (int nt = 0; nt < 8; nt++) {
                    mma16816(acc[mt][nt], ah[mt], bh[nt]);
                    mma16816(acc[mt][nt], al[mt], bh[nt]);
                    mma16816(acc[mt][nt], ah[mt], bl[nt]);
                }
        }
        __syncthreads();
    }

    #pragma unroll
    for (int mt = 0; mt < 2; mt++)
        #pragma unroll
        for (int nt = 0; nt < 8; nt++) {
            int gr = m0 + wm + mt*16 + (lane >> 2);
            int gc = n0 + wn + nt*8 + (lane & 3) * 2;
            epi_pair<EPI,RELUF,WRITET>(acc[mt][nt][0], acc[mt][nt][1], gr,     gc,
                                       bias1, tbuf, sgbuf, outF, outH, outL);
            epi_pair<EPI,RELUF,WRITET>(acc[mt][nt][2], acc[mt][nt][3], gr + 8, gc,
                                       bias1, tbuf, sgbuf, outF, outH, outL);
        }
}

// ---------------- RQ spline + feature product ----------------
__device__ __forceinline__ float softplusf(float x) {
    return fmaxf(x, 0.f) + log1pf(expf(-fabsf(x)));
}

__global__ void spline_kernel(const float* __restrict__ P, const float* __restrict__ pred,
                              float* __restrict__ out) {
    int b = blockIdx.x;
    int f = threadIdx.x;
    const float* p = P + (size_t)b * NOUTP + f * MP_;
    float x = pred[b * F_ + f];

    float cdf;
    if (x == 1.0f) {
        cdf = 1.0f;
    } else {
        const float scale = 0.04419417382415922f;  // 1/sqrt(512)
        float ew[NBINS], mx = -1e30f;
        #pragma unroll
        for (int k = 0; k < NBINS; k++) { ew[k] = p[k] * scale; mx = fmaxf(mx, ew[k]); }
        float s = 0.f;
        #pragma unroll
        for (int k = 0; k < NBINS; k++) { ew[k] = expf(ew[k] - mx); s += ew[k]; }
        float inv = (1.f - 1e-3f * NBINS) / s;
        float cw[NBINS + 1];
        cw[0] = 0.f;
        float run = 0.f;
        #pragma unroll
        for (int k = 0; k < NBINS; k++) { run += 1e-3f + ew[k] * inv; cw[k + 1] = run; }
        cw[NBINS] = 1.f;

        float eh[NBINS];
        mx = -1e30f;
        #pragma unroll
        for (int k = 0; k < NBINS; k++) { eh[k] = p[NBINS + k] * scale; mx = fmaxf(mx, eh[k]); }
        s = 0.f;
        #pragma unroll
        for (int k = 0; k < NBINS; k++) { eh[k] = expf(eh[k] - mx); s += eh[k]; }
        inv = (1.f - 1e-3f * NBINS) / s;
        float ch[NBINS + 1];
        ch[0] = 0.f;
        run = 0.f;
        #pragma unroll
        for (int k = 0; k < NBINS; k++) { run += 1e-3f + eh[k] * inv; ch[k + 1] = run; }
        ch[NBINS] = 1.f;

        int cnt = 0;
        #pragma unroll
        for (int k = 0; k <= NBINS; k++) {
            float loc = (k == NBINS) ? (1.f + 1e-6f) : cw[k];
            cnt += (x >= loc) ? 1 : 0;
        }
        int idx = min(max(cnt - 1, 0), NBINS - 1);

        float in_cw = cw[idx], in_w = cw[idx + 1] - cw[idx];
        float in_ch = ch[idx], in_h = ch[idx + 1] - ch[idx];
        float d0 = 1e-3f + softplusf(p[2 * NBINS + idx]);
        float d1 = 1e-3f + softplusf(p[2 * NBINS + idx + 1]);

        float delta = in_h / in_w;
        float theta = (x - in_cw) / in_w;
        float tt = theta * (1.f - theta);
        float num = in_h * (delta * theta * theta + d0 * tt);
        float den = delta + (d0 + d1 - 2.f * delta) * tt;
        cdf = in_ch + num / den;
    }

    double vv = (double)cdf;
    #pragma unroll
    for (int o = 16; o > 0; o >>= 1)
        vv *= __shfl_xor_sync(0xffffffffu, vv, o);

    __shared__ double sred[2];
    int w = threadIdx.x >> 5;
    if ((threadIdx.x & 31) == 0) sred[w] = vv;
    __syncthreads();
    if (threadIdx.x == 0) out[b] = (float)(sred[0] * sred[1]);
}

// ---------------- launch ----------------
extern "C" void kernel_launch(void* const* d_in, const int* in_sizes, int n_in,
                              void* d_out, int out_size) {
    const float* pred  = (const float*)d_in[0];
    const float* ctx   = (const float*)d_in[1];
    const float* W_in  = (const float*)d_in[2];
    const float* b_in  = (const float*)d_in[3];
    const float* Wc_in = (const float*)d_in[4];
    const float* bc_in = (const float*)d_in[5];
    const float* Wb1   = (const float*)d_in[6];
    const float* bb1   = (const float*)d_in[7];
    const float* Wb2   = (const float*)d_in[8];
    const float* bb2   = (const float*)d_in[9];
    const float* Wcb   = (const float*)d_in[10];
    const float* bcb   = (const float*)d_in[11];
    const float* W_out = (const float*)d_in[12];
    const float* b_out = (const float*)d_in[13];
    float* out = (float*)d_out;

    cudaFuncSetAttribute(gemm_bf3<0,false,false,0>, cudaFuncAttributeMaxDynamicSharedMemorySize, SMEM_SZ);
    cudaFuncSetAttribute(gemm_bf3<1,false,false,1>, cudaFuncAttributeMaxDynamicSharedMemorySize, SMEM_SZ);
    cudaFuncSetAttribute(gemm_bf3<2,false,false,0>, cudaFuncAttributeMaxDynamicSharedMemorySize, SMEM_SZ);
    cudaFuncSetAttribute(gemm_bf3<3,true, true ,1>, cudaFuncAttributeMaxDynamicSharedMemorySize, SMEM_SZ);
    cudaFuncSetAttribute(gemm_bf3<3,false,true ,1>, cudaFuncAttributeMaxDynamicSharedMemorySize, SMEM_SZ);
    cudaFuncSetAttribute(gemm_bf3<4,false,false,2>, cudaFuncAttributeMaxDynamicSharedMemorySize, SMEM_SZ);

    __nv_bfloat16 *Ah, *Al, *Xh, *Xl, *Yh, *Yl;
    __nv_bfloat16 *Wch, *Wcl, *Whh, *Whl, *Wbh, *Wbl, *Woh, *Wol;
    float *t, *sg, *P, *pb;
    cudaGetSymbolAddress((void**)&Ah, g_Ah);   cudaGetSymbolAddress((void**)&Al, g_Al);
    cudaGetSymbolAddress((void**)&Xh, g_Xh);   cudaGetSymbolAddress((void**)&Xl, g_Xl);
    cudaGetSymbolAddress((void**)&Yh, g_Yh);   cudaGetSymbolAddress((void**)&Yl, g_Yl);
    cudaGetSymbolAddress((void**)&Wch, g_Wcat_h); cudaGetSymbolAddress((void**)&Wcl, g_Wcat_l);
    cudaGetSymbolAddress((void**)&Whh, g_Whh_h);  cudaGetSymbolAddress((void**)&Whl, g_Whh_l);
    cudaGetSymbolAddress((void**)&Wbh, g_Wcb_h);  cudaGetSymbolAddress((void**)&Wbl, g_Wcb_l);
    cudaGetSymbolAddress((void**)&Woh, g_Wout_h); cudaGetSymbolAddress((void**)&Wol, g_Wout_l);
    cudaGetSymbolAddress((void**)&t, g_t);
    cudaGetSymbolAddress((void**)&sg, g_sg);
    cudaGetSymbolAddress((void**)&P, g_P);
    cudaGetSymbolAddress((void**)&pb, g_pb);

    // 1) preps (masked, degree-sorted hidden dim, hi/lo split)
    prepA   <<<(B_*KIN + 255) / 256, 256>>>(pred, ctx);
    prepWcat<<<(H_*KIN + 255) / 256, 256>>>(W_in, Wc_in);
    prepWhh <<<(2*NBLK*HH + 255) / 256, 256>>>(Wb1, Wb2);
    prepWcb <<<(NBLK*HH + 255) / 256, 256>>>(Wcb);
    prepWout<<<((int)(((size_t)NOUTP*H_ + 255) / 256)), 256>>>(W_out);
    permB   <<<(10*H_ + 255) / 256, 256>>>(b_in, bc_in, bb1, bb2, bcb);

    dim3 gH(H_ / BN, B_ / BM);   // (4, 128)

    // 2) t = [pred|ctx] @ Wcat + biases ; X = split(relu(t)); tbuf = t   (full K)
    gemm_bf3<0,false,false,0><<<gH, 256, SMEM_SZ>>>(Ah, Al, KIN, Wch, Wcl, KIN,
        pb, t, nullptr, nullptr, Xh, Xl);

    // 3) residual blocks
    for (int i = 0; i < NBLK; i++) {
        gemm_bf3<1,false,false,1><<<gH, 256, SMEM_SZ>>>(Xh, Xl, H_,
            Whh + (size_t)i*HH, Whl + (size_t)i*HH, H_,
            pb + (1+i)*H_, nullptr, nullptr, nullptr, Yh, Yl);
        gemm_bf3<2,false,false,0><<<gH, 256, SMEM_SZ>>>(Ah + F_, Al + F_, KIN,
            Wbh + (size_t)i*HH, Wbl + (size_t)i*HH, C_,
            pb + (7+i)*H_, nullptr, sg, nullptr, nullptr, nullptr);
        if (i < NBLK - 1)
            gemm_bf3<3,true,true,1><<<gH, 256, SMEM_SZ>>>(Yh, Yl, H_,
                Whh + (size_t)(NBLK + i)*HH, Whl + (size_t)(NBLK + i)*HH, H_,
                pb + (4+i)*H_, t, sg, nullptr, Xh, Xl);
        else
            gemm_bf3<3,false,true,1><<<gH, 256, SMEM_SZ>>>(Yh, Yl, H_,
                Whh + (size_t)(NBLK + i)*HH, Whl + (size_t)(NBLK + i)*HH, H_,
                pb + (4+i)*H_, t, sg, nullptr, Xh, Xl);
    }

    // 4) P = t @ WoutM + b_out (degree-limited K per feature tile)
    dim3 gO(NOUTP / BN, B_ / BM);  // (48, 128)
    gemm_bf3<4,false,false,2><<<gO, 256, SMEM_SZ>>>(Xh, Xl, H_, Woh, Wol, H_,
        b_out, nullptr, nullptr, P, nullptr, nullptr);

    // 5) spline + product
    spline_kernel<<<B_, F_>>>(P, pred, out);
}